// round 15
// baseline (speedup 1.0000x reference)
#include <cuda_runtime.h>
#include <cuda_fp16.h>
#include <cstdint>

#define FDIM    128
#define TP      64
#define NTHR    256
#define NLAYERS 8
#define NGEMM   16
#define OMEGA_W 30.0f

// ---------------- smem layout (bytes) ----------------
#define SMEM_MB_W0   0
#define SMEM_MB_W1   8
#define SMEM_CNT     16                    // 16 int counters
#define SMEM_CS      192                   // 64*3 floats coords (768 B)
#define SMEM_YBUF    1024                  // 4 wm x 64 floats (1 KB)
#define SMEM_X       2048                  // X [buf][128 f][64 n] fp16: 2 x 16 KB
#define SMEM_WBUF0   34816                 // weight buf 0 (32 KB)
#define SMEM_WBUF1   67584                 // weight buf 1 (32 KB)
#define SMEM_TOTAL   100352                // x2 CTAs = 196 KB <= 228 KB/SM

// Pre-converted, pre-swizzled fp16 weights: [gemm][128*128]
__device__ __align__(128) __half g_W[NGEMM][FDIM * FDIM];

// ---------------- PTX helpers ----------------
__device__ __forceinline__ uint32_t smem_u32(const void* p) {
    uint32_t a;
    asm("{ .reg .u64 t; cvta.to.shared.u64 t, %1; cvt.u32.u64 %0, t; }" : "=r"(a) : "l"(p));
    return a;
}
#define MBAR_INIT(mbar, cnt) \
    asm volatile("mbarrier.init.shared.b64 [%0], %1;" :: "r"(mbar), "r"(cnt) : "memory")
#define MBAR_EXPECT_TX(mbar, bytes) \
    asm volatile("mbarrier.arrive.expect_tx.shared.b64 _, [%0], %1;" :: "r"(mbar), "r"(bytes) : "memory")
#define MBAR_WAIT(mbar, ph) do {                                              \
    asm volatile("{\n\t.reg .pred P1;\n\t"                                    \
        "WL_%=:\n\t"                                                          \
        "mbarrier.try_wait.parity.acquire.cta.shared::cta.b64 P1, [%0], %1, 0x989680;\n\t" \
        "@P1 bra.uni WD_%=;\n\t"                                              \
        "bra.uni WL_%=;\n\t"                                                  \
        "WD_%=:\n\t}"                                                         \
        :: "r"(mbar), "r"(ph) : "memory");                                    \
} while (0)
#define BULK_G2S(dst, src, bytes, mbar) \
    asm volatile("cp.async.bulk.shared::cluster.global.mbarrier::complete_tx::bytes [%0], [%1], %2, [%3];" \
        :: "r"(dst), "l"(src), "r"(bytes), "r"(mbar) : "memory")
#define BAR_HALF(id) asm volatile("bar.sync %0, 128;" :: "r"(id) : "memory")

#define LDSM_X4(r, addr) \
    asm volatile("ldmatrix.sync.aligned.m8n8.x4.shared.b16 {%0,%1,%2,%3}, [%4];" \
        : "=r"((r)[0]), "=r"((r)[1]), "=r"((r)[2]), "=r"((r)[3]) : "r"(addr))
#define LDSM_X4T(r, addr) \
    asm volatile("ldmatrix.sync.aligned.m8n8.x4.trans.shared.b16 {%0,%1,%2,%3}, [%4];" \
        : "=r"((r)[0]), "=r"((r)[1]), "=r"((r)[2]), "=r"((r)[3]) : "r"(addr))

#define MMA16816(d, a, b0, b1) \
    asm volatile("mma.sync.aligned.m16n8k16.row.col.f32.f16.f16.f32 " \
        "{%0,%1,%2,%3},{%4,%5,%6,%7},{%8,%9},{%0,%1,%2,%3};" \
        : "+f"((d)[0]), "+f"((d)[1]), "+f"((d)[2]), "+f"((d)[3]) \
        : "r"((a)[0]), "r"((a)[1]), "r"((a)[2]), "r"((a)[3]), "r"(b0), "r"(b1))

// Weight tile: rows 256 B (128 fp16), XOR swizzle
__device__ __forceinline__ uint32_t woff(int f, int k) {
    return (uint32_t)(f * 256 + ((2 * k) ^ ((f & 7) << 4)));
}
// Activation tile: rows 128 B (64 fp16), XOR swizzle
__device__ __forceinline__ uint32_t xo64(int f, int n) {
    return (uint32_t)(f * 128 + ((2 * n) ^ ((f & 7) << 4)));
}
__device__ __forceinline__ void store_h16(char* xb, int f, int n, float v0, float v1) {
    *reinterpret_cast<__half2*>(xb + xo64(f, n)) = __floats2half2_rn(v0, v1);
}

// ---------------- weight prep: fp32 -> fp16, swizzled ----------------
__global__ void prep_weights_kernel(const float* __restrict__ W1,
                                    const float* __restrict__ W2) {
    int g = blockIdx.x;
    int layer = g >> 1;
    const float* src = ((g & 1) ? W2 : W1) + layer * FDIM * FDIM;
    for (int idx = threadIdx.x; idx < FDIM * FDIM; idx += blockDim.x) {
        int f = idx >> 7;
        int k = idx & 127;
        g_W[g][f * FDIM + (k ^ ((f & 7) << 3))] = __float2half_rn(src[idx]);
    }
}

// ---------------- main kernel ----------------
__global__ __launch_bounds__(NTHR, 2)
void siren_mma_kernel(const float* __restrict__ coords,
                      const float* __restrict__ W_first,
                      const float* __restrict__ b_first,
                      const float* __restrict__ b1,
                      const float* __restrict__ b2,
                      const float* __restrict__ W_out,
                      const float* __restrict__ b_out,
                      float* __restrict__ out, int N) {
    extern __shared__ char smem[];
    const uint32_t sb = smem_u32(smem);
    float* cs = (float*)(smem + SMEM_CS);
    int* cnt = (int*)(smem + SMEM_CNT);

    const int tid  = threadIdx.x;
    const int w    = tid >> 5;
    const int lane = tid & 31;
    const int wm   = w & 3;                // M group: features [32*wm, 32*wm+32)
    const int nh   = w >> 2;               // point half (32 pts) 0/1
    const int f0   = wm << 5;
    const int n0   = nh << 5;              // 0 or 32 (column base in X tile)
    const int tg   = lane >> 2;
    const int t4   = lane & 3;
    const int li   = lane >> 3;
    const int lr   = lane & 7;
    const int P0   = blockIdx.x * TP;
    const int barid = 1 + nh;

    // X double buffer (shared tile, halves own disjoint columns)
    char* xbase = smem + SMEM_X;
    const uint32_t xbaseu = sb + SMEM_X;

    if (tid == 0) {
        MBAR_INIT(sb + SMEM_MB_W0, 1);
        MBAR_INIT(sb + SMEM_MB_W1, 1);
    }
    if (tid < NGEMM) cnt[tid] = 0;
    for (int t = tid; t < 3 * TP; t += NTHR) {
        int p = t / 3, dd = t - p * 3;
        int pg = min(P0 + p, N - 1);
        cs[t] = coords[pg * 3 + dd];
    }
    __syncthreads();

    if (tid == 0) {
        MBAR_EXPECT_TX(sb + SMEM_MB_W0, 32768u);
        BULK_G2S(sb + SMEM_WBUF0, (const void*)&g_W[0][0], 32768u, sb + SMEM_MB_W0);
        MBAR_EXPECT_TX(sb + SMEM_MB_W1, 32768u);
        BULK_G2S(sb + SMEM_WBUF1, (const void*)&g_W[1][0], 32768u, sb + SMEM_MB_W1);
    }

    // rows this thread owns: ra = f0 + 16*mi + tg, rb = ra + 8
    // points: n = n0 + ni*8 + t4*2 (+1), ni 0..3
    float h[2][4][4];        // residual [mi][ni][c]
    float d[2][4][4];        // accum    [mi][ni][c]

    // ---- first layer (fp32) -> X buf0 ----
#pragma unroll
    for (int mi = 0; mi < 2; mi++) {
        const int ra = f0 + 16 * mi + tg, rb = ra + 8;
        const float wa0 = __ldg(&W_first[ra * 3]), wa1 = __ldg(&W_first[ra * 3 + 1]),
                    wa2 = __ldg(&W_first[ra * 3 + 2]);
        const float wb0 = __ldg(&W_first[rb * 3]), wb1 = __ldg(&W_first[rb * 3 + 1]),
                    wb2 = __ldg(&W_first[rb * 3 + 2]);
        const float ba = __ldg(&b_first[ra]), bb = __ldg(&b_first[rb]);
#pragma unroll
        for (int ni = 0; ni < 4; ni++) {
            const int n = n0 + ni * 8 + t4 * 2;
            float x0 = cs[n * 3], y0 = cs[n * 3 + 1], z0 = cs[n * 3 + 2];
            float x1 = cs[n * 3 + 3], y1 = cs[n * 3 + 4], z1 = cs[n * 3 + 5];
            h[mi][ni][0] = __sinf(OMEGA_W * fmaf(wa0, x0, fmaf(wa1, y0, fmaf(wa2, z0, ba))));
            h[mi][ni][1] = __sinf(OMEGA_W * fmaf(wa0, x1, fmaf(wa1, y1, fmaf(wa2, z1, ba))));
            h[mi][ni][2] = __sinf(OMEGA_W * fmaf(wb0, x0, fmaf(wb1, y0, fmaf(wb2, z0, bb))));
            h[mi][ni][3] = __sinf(OMEGA_W * fmaf(wb0, x1, fmaf(wb1, y1, fmaf(wb2, z1, bb))));
            store_h16(xbase, ra, n, h[mi][ni][0], h[mi][ni][1]);
            store_h16(xbase, rb, n, h[mi][ni][2], h[mi][ni][3]);
        }
    }
    BAR_HALF(barid);

    int wph0 = 0, wph1 = 0;

    for (int g = 0; g < NGEMM; g++) {
        const int layer = g >> 1;
        const bool even = ((g & 1) == 0);

        {   // wait for W(g)
            uint32_t mb = sb + ((g & 1) ? SMEM_MB_W1 : SMEM_MB_W0);
            int ph = (g & 1) ? wph1 : wph0;
            MBAR_WAIT(mb, ph);
            if (g & 1) wph1 ^= 1; else wph0 ^= 1;
        }

        const uint32_t wbase = sb + ((g & 1) ? SMEM_WBUF1 : SMEM_WBUF0);
        const uint32_t xr = xbaseu + (uint32_t)(g & 1) * 16384u;     // MMA reads
        char* xw = xbase + (1 - (g & 1)) * 16384;                    // epi writes

#pragma unroll
        for (int mi = 0; mi < 2; mi++)
#pragma unroll
            for (int ni = 0; ni < 4; ni++)
                d[mi][ni][0] = d[mi][ni][1] = d[mi][ni][2] = d[mi][ni][3] = 0.f;

        // ---- single-product fp16 MMA: M=32 x N=32 x K=128 per warp ----
#pragma unroll
        for (int kk = 0; kk < 8; kk++) {
            const int k0 = kk << 4;
            uint32_t a[2][4];
#pragma unroll
            for (int mi = 0; mi < 2; mi++) {
                const int arow = f0 + 16 * mi + ((li & 1) << 3) + lr;
                const int acol = k0 + ((li >> 1) << 3);
                LDSM_X4(a[mi], wbase + woff(arow, acol));
            }
            const int krow = k0 + ((li & 1) << 3) + lr;
            uint32_t b[2][4];
#pragma unroll
            for (int q = 0; q < 2; q++) {
                const int ncol = n0 + q * 16 + ((li >> 1) << 3);
                LDSM_X4T(b[q], xr + xo64(krow, ncol));
            }
#pragma unroll
            for (int mi = 0; mi < 2; mi++)
#pragma unroll
                for (int q = 0; q < 2; q++) {
                    MMA16816(d[mi][2 * q],     a[mi], b[q][0], b[q][1]);
                    MMA16816(d[mi][2 * q + 1], a[mi], b[q][2], b[q][3]);
                }
        }

        // W(g) consumption tracking; last warp launches prefetch of g+2
        if (lane == 0) {
            int old = atomicAdd(&cnt[g], 1);
            if (old == 7 && g + 2 < NGEMM) {
                uint32_t mb = sb + ((g & 1) ? SMEM_MB_W1 : SMEM_MB_W0);
                uint32_t wbuf = sb + ((g & 1) ? SMEM_WBUF1 : SMEM_WBUF0);
                MBAR_EXPECT_TX(mb, 32768u);
                BULK_G2S(wbuf, (const void*)&g_W[g + 2][0], 32768u, mb);
            }
        }

        if (g < NGEMM - 1) {
            // ---- epilogue -> X write buffer (disjoint from read buffer) ----
#pragma unroll
            for (int mi = 0; mi < 2; mi++) {
                const int ra = f0 + 16 * mi + tg, rb = ra + 8;
                float ba, bb;
                if (even) {
                    ba = __ldg(&b1[layer * FDIM + ra]);
                    bb = __ldg(&b1[layer * FDIM + rb]);
                } else {
                    ba = __ldg(&b2[layer * FDIM + ra]);
                    bb = __ldg(&b2[layer * FDIM + rb]);
                }
                const float w_in = (even && layer > 0) ? 0.5f : 1.0f;
#pragma unroll
                for (int ni = 0; ni < 4; ni++) {
                    const int n = n0 + ni * 8 + t4 * 2;
                    if (even) {
                        float s00 = __sinf(OMEGA_W * fmaf(w_in, d[mi][ni][0], ba));
                        float s01 = __sinf(OMEGA_W * fmaf(w_in, d[mi][ni][1], ba));
                        float s10 = __sinf(OMEGA_W * fmaf(w_in, d[mi][ni][2], bb));
                        float s11 = __sinf(OMEGA_W * fmaf(w_in, d[mi][ni][3], bb));
                        store_h16(xw, ra, n, s00, s01);
                        store_h16(xw, rb, n, s10, s11);
                    } else {
                        h[mi][ni][0] += __sinf(OMEGA_W * (d[mi][ni][0] + ba));
                        h[mi][ni][1] += __sinf(OMEGA_W * (d[mi][ni][1] + ba));
                        h[mi][ni][2] += __sinf(OMEGA_W * (d[mi][ni][2] + bb));
                        h[mi][ni][3] += __sinf(OMEGA_W * (d[mi][ni][3] + bb));
                        store_h16(xw, ra, n, h[mi][ni][0], h[mi][ni][1]);
                        store_h16(xw, rb, n, h[mi][ni][2], h[mi][ni][3]);
                    }
                }
            }
            BAR_HALF(barid);   // epi writes visible to this half before MMA(g+1)
        } else {
            // ---- final epilogue: h = 0.5*(h+s2), output GEMV ----
            float* ybuf = (float*)(smem + SMEM_YBUF);
            float p0s[4], p1s[4];
#pragma unroll
            for (int ni = 0; ni < 4; ni++) { p0s[ni] = 0.f; p1s[ni] = 0.f; }
#pragma unroll
            for (int mi = 0; mi < 2; mi++) {
                const int ra = f0 + 16 * mi + tg, rb = ra + 8;
                const float ba = __ldg(&b2[layer * FDIM + ra]);
                const float bb = __ldg(&b2[layer * FDIM + rb]);
                const float woa = __ldg(&W_out[ra]), wob = __ldg(&W_out[rb]);
#pragma unroll
                for (int ni = 0; ni < 4; ni++) {
                    float h0 = 0.5f * (h[mi][ni][0] + __sinf(OMEGA_W * (d[mi][ni][0] + ba)));
                    float h1 = 0.5f * (h[mi][ni][1] + __sinf(OMEGA_W * (d[mi][ni][1] + ba)));
                    float h2 = 0.5f * (h[mi][ni][2] + __sinf(OMEGA_W * (d[mi][ni][2] + bb)));
                    float h3 = 0.5f * (h[mi][ni][3] + __sinf(OMEGA_W * (d[mi][ni][3] + bb)));
                    p0s[ni] += fmaf(h0, woa, h2 * wob);
                    p1s[ni] += fmaf(h1, woa, h3 * wob);
                }
            }
#pragma unroll
            for (int ni = 0; ni < 4; ni++) {
                float p0 = p0s[ni], p1 = p1s[ni];
#pragma unroll
                for (int m = 4; m <= 16; m <<= 1) {
                    p0 += __shfl_xor_sync(0xffffffffu, p0, m);
                    p1 += __shfl_xor_sync(0xffffffffu, p1, m);
                }
                if (tg == 0) {
                    const int n = n0 + ni * 8 + t4 * 2;
                    *reinterpret_cast<float2*>(&ybuf[wm * TP + n]) = make_float2(p0, p1);
                }
            }
        }
    }
    __syncthreads();

    // ---- cross-warp output reduction (64 points) ----
    if (tid < TP) {
        int p = tid;
        if (P0 + p < N) {
            float* ybuf = (float*)(smem + SMEM_YBUF);
            float y = __ldg(&b_out[0]) + ybuf[p] + ybuf[TP + p]
                    + ybuf[2 * TP + p] + ybuf[3 * TP + p];
            out[P0 + p] = y;
        }
    }
}

extern "C" void kernel_launch(void* const* d_in, const int* in_sizes, int n_in,
                              void* d_out, int out_size) {
    const float* coords  = (const float*)d_in[0];
    const float* W_first = (const float*)d_in[1];
    const float* b_first = (const float*)d_in[2];
    const float* W1      = (const float*)d_in[3];
    const float* b1      = (const float*)d_in[4];
    const float* W2      = (const float*)d_in[5];
    const float* b2      = (const float*)d_in[6];
    const float* W_out   = (const float*)d_in[7];
    const float* b_out   = (const float*)d_in[8];
    const int N = in_sizes[0] / 3;

    prep_weights_kernel<<<NGEMM, 256>>>(W1, W2);

    cudaFuncSetAttribute(siren_mma_kernel,
                         cudaFuncAttributeMaxDynamicSharedMemorySize, SMEM_TOTAL);

    const int nblocks = (N + TP - 1) / TP;
    siren_mma_kernel<<<nblocks, NTHR, SMEM_TOTAL>>>(coords, W_first, b_first,
                                                    b1, b2, W_out, b_out,
                                                    (float*)d_out, N);
}

// round 16
// speedup vs baseline: 1.0324x; 1.0324x over previous
#include <cuda_runtime.h>
#include <cuda_fp16.h>
#include <cstdint>

#define FDIM    128
#define TP      128
#define NTHR    256
#define NLAYERS 8
#define NGEMM   16
#define OMEGA_W 30.0f
#define SKEW_CYC 1600u

// ---------------- smem layout (bytes) ----------------
#define SMEM_MB_W0   0
#define SMEM_MB_W1   8
#define SMEM_CNT     64                    // 16 int counters
#define SMEM_CS      192                   // 128*3 floats coords (1536 B)
#define SMEM_YBUF    2048                  // [2][4][64] floats (2 KB)
#define SMEM_X       4096                  // [hf][buf] 4 x 16 KB fp16
#define SMEM_WBUF0   69632                 // weight buf 0 (32 KB)
#define SMEM_WBUF1   102400                // weight buf 1 (32 KB)
#define SMEM_TOTAL   135168

// Pre-converted, pre-swizzled fp16 weights: [gemm][128*128]
__device__ __align__(128) __half g_W[NGEMM][FDIM * FDIM];

// ---------------- PTX helpers ----------------
__device__ __forceinline__ uint32_t smem_u32(const void* p) {
    uint32_t a;
    asm("{ .reg .u64 t; cvta.to.shared.u64 t, %1; cvt.u32.u64 %0, t; }" : "=r"(a) : "l"(p));
    return a;
}
#define MBAR_INIT(mbar, cnt) \
    asm volatile("mbarrier.init.shared.b64 [%0], %1;" :: "r"(mbar), "r"(cnt) : "memory")
#define MBAR_EXPECT_TX(mbar, bytes) \
    asm volatile("mbarrier.arrive.expect_tx.shared.b64 _, [%0], %1;" :: "r"(mbar), "r"(bytes) : "memory")
#define MBAR_WAIT(mbar, ph) do {                                              \
    asm volatile("{\n\t.reg .pred P1;\n\t"                                    \
        "WL_%=:\n\t"                                                          \
        "mbarrier.try_wait.parity.acquire.cta.shared::cta.b64 P1, [%0], %1, 0x989680;\n\t" \
        "@P1 bra.uni WD_%=;\n\t"                                              \
        "bra.uni WL_%=;\n\t"                                                  \
        "WD_%=:\n\t}"                                                         \
        :: "r"(mbar), "r"(ph) : "memory");                                    \
} while (0)
#define BULK_G2S(dst, src, bytes, mbar) \
    asm volatile("cp.async.bulk.shared::cluster.global.mbarrier::complete_tx::bytes [%0], [%1], %2, [%3];" \
        :: "r"(dst), "l"(src), "r"(bytes), "r"(mbar) : "memory")
#define BAR_HALF(id) asm volatile("bar.sync %0, 128;" :: "r"(id) : "memory")

#define LDSM_X4(r, addr) \
    asm volatile("ldmatrix.sync.aligned.m8n8.x4.shared.b16 {%0,%1,%2,%3}, [%4];" \
        : "=r"((r)[0]), "=r"((r)[1]), "=r"((r)[2]), "=r"((r)[3]) : "r"(addr))
#define LDSM_X4T(r, addr) \
    asm volatile("ldmatrix.sync.aligned.m8n8.x4.trans.shared.b16 {%0,%1,%2,%3}, [%4];" \
        : "=r"((r)[0]), "=r"((r)[1]), "=r"((r)[2]), "=r"((r)[3]) : "r"(addr))

#define MMA16816(d, a, b0, b1) \
    asm volatile("mma.sync.aligned.m16n8k16.row.col.f32.f16.f16.f32 " \
        "{%0,%1,%2,%3},{%4,%5,%6,%7},{%8,%9},{%0,%1,%2,%3};" \
        : "+f"((d)[0]), "+f"((d)[1]), "+f"((d)[2]), "+f"((d)[3]) \
        : "r"((a)[0]), "r"((a)[1]), "r"((a)[2]), "r"((a)[3]), "r"(b0), "r"(b1))

// Weight tile: rows 256 B (128 fp16), XOR swizzle
__device__ __forceinline__ uint32_t woff(int f, int k) {
    return (uint32_t)(f * 256 + ((2 * k) ^ ((f & 7) << 4)));
}
// Activation half-tile: rows 128 B (64 fp16), XOR swizzle
__device__ __forceinline__ uint32_t xo64(int f, int n) {
    return (uint32_t)(f * 128 + ((2 * n) ^ ((f & 7) << 4)));
}
__device__ __forceinline__ void store_h16(char* xb, int f, int n, float v0, float v1) {
    *reinterpret_cast<__half2*>(xb + xo64(f, n)) = __floats2half2_rn(v0, v1);
}

// ---------------- weight prep: fp32 -> fp16, swizzled ----------------
__global__ void prep_weights_kernel(const float* __restrict__ W1,
                                    const float* __restrict__ W2) {
    int g = blockIdx.x;
    int layer = g >> 1;
    const float* src = ((g & 1) ? W2 : W1) + layer * FDIM * FDIM;
    for (int idx = threadIdx.x; idx < FDIM * FDIM; idx += blockDim.x) {
        int f = idx >> 7;
        int k = idx & 127;
        g_W[g][f * FDIM + (k ^ ((f & 7) << 3))] = __float2half_rn(src[idx]);
    }
}

// ---------------- main kernel ----------------
__global__ __launch_bounds__(NTHR, 1)
void siren_mma_kernel(const float* __restrict__ coords,
                      const float* __restrict__ W_first,
                      const float* __restrict__ b_first,
                      const float* __restrict__ b1,
                      const float* __restrict__ b2,
                      const float* __restrict__ W_out,
                      const float* __restrict__ b_out,
                      float* __restrict__ out, int N) {
    extern __shared__ char smem[];
    const uint32_t sb = smem_u32(smem);
    float* cs = (float*)(smem + SMEM_CS);
    int* cnt = (int*)(smem + SMEM_CNT);

    const int tid  = threadIdx.x;
    const int w    = tid >> 5;
    const int lane = tid & 31;
    const int wm   = w & 3;                // M group: features [32*wm, 32*wm+32)
    const int hf   = w >> 2;               // point half 0/1
    const int f0   = wm << 5;
    const int n0   = hf << 6;
    const int tg   = lane >> 2;
    const int t4   = lane & 3;
    const int li   = lane >> 3;
    const int lr   = lane & 7;
    const int P0   = blockIdx.x * TP;
    const int barid = 1 + hf;

    // X double buffer for this half: read buf = g&1, write buf = 1-(g&1)
    char* xhalf = smem + SMEM_X + hf * 32768;
    const uint32_t xhalfu = sb + SMEM_X + hf * 32768;

    if (tid == 0) {
        MBAR_INIT(sb + SMEM_MB_W0, 1);
        MBAR_INIT(sb + SMEM_MB_W1, 1);
    }
    if (tid < NGEMM) cnt[tid] = 0;
    for (int t = tid; t < 3 * TP; t += NTHR) {
        int p = t / 3, dd = t - p * 3;
        int pg = min(P0 + p, N - 1);
        cs[t] = coords[pg * 3 + dd];
    }
    __syncthreads();

    if (tid == 0) {
        MBAR_EXPECT_TX(sb + SMEM_MB_W0, 32768u);
        BULK_G2S(sb + SMEM_WBUF0, (const void*)&g_W[0][0], 32768u, sb + SMEM_MB_W0);
        MBAR_EXPECT_TX(sb + SMEM_MB_W1, 32768u);
        BULK_G2S(sb + SMEM_WBUF1, (const void*)&g_W[1][0], 32768u, sb + SMEM_MB_W1);
    }

    // rows this thread owns: f0 + 16*mi + tg (+8)
    float h[2][8][4];

    // ---- first layer (fp32) -> X buf0 ----
#pragma unroll
    for (int mi = 0; mi < 2; mi++) {
        const int ra = f0 + 16 * mi + tg, rb = ra + 8;
        const float wa0 = __ldg(&W_first[ra * 3]), wa1 = __ldg(&W_first[ra * 3 + 1]),
                    wa2 = __ldg(&W_first[ra * 3 + 2]);
        const float wb0 = __ldg(&W_first[rb * 3]), wb1 = __ldg(&W_first[rb * 3 + 1]),
                    wb2 = __ldg(&W_first[rb * 3 + 2]);
        const float ba = __ldg(&b_first[ra]), bb = __ldg(&b_first[rb]);
#pragma unroll
        for (int ni = 0; ni < 8; ni++) {
            const int nl = 8 * ni + t4 * 2;
            const int p = n0 + nl;
            float x0 = cs[p * 3], y0 = cs[p * 3 + 1], z0 = cs[p * 3 + 2];
            float x1 = cs[p * 3 + 3], y1 = cs[p * 3 + 4], z1 = cs[p * 3 + 5];
            h[mi][ni][0] = __sinf(OMEGA_W * fmaf(wa0, x0, fmaf(wa1, y0, fmaf(wa2, z0, ba))));
            h[mi][ni][1] = __sinf(OMEGA_W * fmaf(wa0, x1, fmaf(wa1, y1, fmaf(wa2, z1, ba))));
            h[mi][ni][2] = __sinf(OMEGA_W * fmaf(wb0, x0, fmaf(wb1, y0, fmaf(wb2, z0, bb))));
            h[mi][ni][3] = __sinf(OMEGA_W * fmaf(wb0, x1, fmaf(wb1, y1, fmaf(wb2, z1, bb))));
            store_h16(xhalf, ra, nl, h[mi][ni][0], h[mi][ni][1]);
            store_h16(xhalf, rb, nl, h[mi][ni][2], h[mi][ni][3]);
        }
    }
    BAR_HALF(barid);

    // anti-phase skew (kept from R13 base)
    if (hf == 1) {
        uint32_t t0, t1;
        asm volatile("mov.u32 %0, %%clock;" : "=r"(t0));
        do { asm volatile("mov.u32 %0, %%clock;" : "=r"(t1)); } while (t1 - t0 < SKEW_CYC);
    }

    int wph0 = 0, wph1 = 0;

    for (int g = 0; g < NGEMM; g++) {
        const int layer = g >> 1;
        const bool even = ((g & 1) == 0);

        {   // wait for W(g)
            uint32_t mb = sb + ((g & 1) ? SMEM_MB_W1 : SMEM_MB_W0);
            int ph = (g & 1) ? wph1 : wph0;
            MBAR_WAIT(mb, ph);
            if (g & 1) wph1 ^= 1; else wph0 ^= 1;
        }

        const uint32_t wbase = sb + ((g & 1) ? SMEM_WBUF1 : SMEM_WBUF0);
        const uint32_t xr = xhalfu + (uint32_t)(g & 1) * 16384u;     // MMA reads
        char* xw = xhalf + (1 - (g & 1)) * 16384;                    // epi writes

        float d[2][8][4];
#pragma unroll
        for (int mi = 0; mi < 2; mi++)
#pragma unroll
            for (int ni = 0; ni < 8; ni++)
                d[mi][ni][0] = d[mi][ni][1] = d[mi][ni][2] = d[mi][ni][3] = 0.f;

        // ---- fp16 MMA with FULL A+B ping-pong (k+1 operands loaded before
        //      k's HMMA burst; burst covers LDSM issue+latency) ----
        uint32_t aP[2][4], aQ[2][4], bP[4][4], bQ[4][4];
        const int arow0 = ((li & 1) << 3) + lr;       // row-in-16 component
        const int acol8 = (li >> 1) << 3;
        {   // preload k=0
#pragma unroll
            for (int mi = 0; mi < 2; mi++)
                LDSM_X4(aP[mi], wbase + woff(f0 + 16 * mi + arow0, acol8));
            const int krow = arow0;
#pragma unroll
            for (int q = 0; q < 4; q++)
                LDSM_X4T(bP[q], xr + xo64(krow, q * 16 + acol8));
        }
#pragma unroll
        for (int kk = 0; kk < 8; kk++) {
            uint32_t (*acur)[4] = (kk & 1) ? aQ : aP;
            uint32_t (*anxt)[4] = (kk & 1) ? aP : aQ;
            uint32_t (*bcur)[4] = (kk & 1) ? bQ : bP;
            uint32_t (*bnxt)[4] = (kk & 1) ? bP : bQ;

            if (kk < 7) {   // prefetch k+1 operands (A and B) before the burst
                const int k1 = (kk + 1) << 4;
#pragma unroll
                for (int mi = 0; mi < 2; mi++)
                    LDSM_X4(anxt[mi], wbase + woff(f0 + 16 * mi + arow0, k1 + acol8));
                const int krow1 = k1 + arow0;
#pragma unroll
                for (int q = 0; q < 4; q++)
                    LDSM_X4T(bnxt[q], xr + xo64(krow1, q * 16 + acol8));
            }
#pragma unroll
            for (int mi = 0; mi < 2; mi++)
#pragma unroll
                for (int q = 0; q < 4; q++) {
                    MMA16816(d[mi][2 * q],     acur[mi], bcur[q][0], bcur[q][1]);
                    MMA16816(d[mi][2 * q + 1], acur[mi], bcur[q][2], bcur[q][3]);
                }
        }

        // W(g) consumption tracking; last warp chip-wide launches prefetch of g+2
        if (lane == 0) {
            int old = atomicAdd(&cnt[g], 1);
            if (old == 7 && g + 2 < NGEMM) {
                uint32_t mb = sb + ((g & 1) ? SMEM_MB_W1 : SMEM_MB_W0);
                uint32_t wbuf = sb + ((g & 1) ? SMEM_WBUF1 : SMEM_WBUF0);
                MBAR_EXPECT_TX(mb, 32768u);
                BULK_G2S(wbuf, (const void*)&g_W[g + 2][0], 32768u, mb);
            }
        }

        if (g < NGEMM - 1) {
            // ---- epilogue -> X write buffer (disjoint from read buffer) ----
#pragma unroll
            for (int mi = 0; mi < 2; mi++) {
                const int ra = f0 + 16 * mi + tg, rb = ra + 8;
                float ba, bb;
                if (even) {
                    ba = __ldg(&b1[layer * FDIM + ra]);
                    bb = __ldg(&b1[layer * FDIM + rb]);
                } else {
                    ba = __ldg(&b2[layer * FDIM + ra]);
                    bb = __ldg(&b2[layer * FDIM + rb]);
                }
                const float w_in = (even && layer > 0) ? 0.5f : 1.0f;
#pragma unroll
                for (int ni = 0; ni < 8; ni++) {
                    const int nl = 8 * ni + t4 * 2;
                    if (even) {
                        float s00 = __sinf(OMEGA_W * fmaf(w_in, d[mi][ni][0], ba));
                        float s01 = __sinf(OMEGA_W * fmaf(w_in, d[mi][ni][1], ba));
                        float s10 = __sinf(OMEGA_W * fmaf(w_in, d[mi][ni][2], bb));
                        float s11 = __sinf(OMEGA_W * fmaf(w_in, d[mi][ni][3], bb));
                        store_h16(xw, ra, nl, s00, s01);
                        store_h16(xw, rb, nl, s10, s11);
                    } else {
                        h[mi][ni][0] += __sinf(OMEGA_W * (d[mi][ni][0] + ba));
                        h[mi][ni][1] += __sinf(OMEGA_W * (d[mi][ni][1] + ba));
                        h[mi][ni][2] += __sinf(OMEGA_W * (d[mi][ni][2] + bb));
                        h[mi][ni][3] += __sinf(OMEGA_W * (d[mi][ni][3] + bb));
                        store_h16(xw, ra, nl, h[mi][ni][0], h[mi][ni][1]);
                        store_h16(xw, rb, nl, h[mi][ni][2], h[mi][ni][3]);
                    }
                }
            }
            BAR_HALF(barid);   // epi writes visible before MMA(g+1) reads
        } else {
            // ---- final epilogue: h = 0.5*(h+s2), output GEMV ----
            float* ybuf = (float*)(smem + SMEM_YBUF) + hf * 256;
            float p0s[8], p1s[8];
#pragma unroll
            for (int ni = 0; ni < 8; ni++) { p0s[ni] = 0.f; p1s[ni] = 0.f; }
#pragma unroll
            for (int mi = 0; mi < 2; mi++) {
                const int ra = f0 + 16 * mi + tg, rb = ra + 8;
                const float ba = __ldg(&b2[layer * FDIM + ra]);
                const float bb = __ldg(&b2[layer * FDIM + rb]);
                const float woa = __ldg(&W_out[ra]), wob = __ldg(&W_out[rb]);
#pragma unroll
                for (int ni = 0; ni < 8; ni++) {
                    float h0 = 0.5f * (h[mi][ni][0] + __sinf(OMEGA_W * (d[mi][ni][0] + ba)));
                    float h1 = 0.5f * (h[mi][ni][1] + __sinf(OMEGA_W * (d[mi][ni][1] + ba)));
                    float h2 = 0.5f * (h[mi][ni][2] + __sinf(OMEGA_W * (d[mi][ni][2] + bb)));
                    float h3 = 0.5f * (h[mi][ni][3] + __sinf(OMEGA_W * (d[mi][ni][3] + bb)));
                    p0s[ni] += fmaf(h0, woa, h2 * wob);
                    p1s[ni] += fmaf(h1, woa, h3 * wob);
                }
            }
#pragma unroll
            for (int ni = 0; ni < 8; ni++) {
                float p0 = p0s[ni], p1 = p1s[ni];
#pragma unroll
                for (int m = 4; m <= 16; m <<= 1) {
                    p0 += __shfl_xor_sync(0xffffffffu, p0, m);
                    p1 += __shfl_xor_sync(0xffffffffu, p1, m);
                }
                if (tg == 0) {
                    int nl = 8 * ni + t4 * 2;
                    *reinterpret_cast<float2*>(&ybuf[wm * 64 + nl]) = make_float2(p0, p1);
                }
            }
            BAR_HALF(barid);
        }
    }

    // ---- cross-warp output reduction (per half, 64 points) ----
    {
        const int lih = tid - hf * 128;
        if (lih < 64) {
            int p = n0 + lih;
            if (P0 + p < N) {
                float* ybuf = (float*)(smem + SMEM_YBUF) + hf * 256;
                float y = __ldg(&b_out[0]) + ybuf[lih] + ybuf[64 + lih]
                        + ybuf[128 + lih] + ybuf[192 + lih];
                out[P0 + p] = y;
            }
        }
    }
}

extern "C" void kernel_launch(void* const* d_in, const int* in_sizes, int n_in,
                              void* d_out, int out_size) {
    const float* coords  = (const float*)d_in[0];
    const float* W_first = (const float*)d_in[1];
    const float* b_first = (const float*)d_in[2];
    const float* W1      = (const float*)d_in[3];
    const float* b1      = (const float*)d_in[4];
    const float* W2      = (const float*)d_in[5];
    const float* b2      = (const float*)d_in[6];
    const float* W_out   = (const float*)d_in[7];
    const float* b_out   = (const float*)d_in[8];
    const int N = in_sizes[0] / 3;

    prep_weights_kernel<<<NGEMM, 256>>>(W1, W2);

    cudaFuncSetAttribute(siren_mma_kernel,
                         cudaFuncAttributeMaxDynamicSharedMemorySize, SMEM_TOTAL);

    const int nblocks = (N + TP - 1) / TP;
    siren_mma_kernel<<<nblocks, NTHR, SMEM_TOTAL>>>(coords, W_first, b_first,
                                                    b1, b2, W_out, b_out,
                                                    (float*)d_out, N);
}